// round 7
// baseline (speedup 1.0000x reference)
#include <cuda_runtime.h>

#define BATCH 128
#define NT 512

__device__ float g_partials[BATCH];
__device__ float g_wcol[50];
__device__ unsigned int g_count = 0;
__device__ int g_wflag = 0;

__device__ __forceinline__ float warp_sum(float v) {
#pragma unroll
    for (int o = 16; o; o >>= 1) v += __shfl_down_sync(0xffffffffu, v, o);
    return v;
}

// grid = BATCH+1. Blocks 0..127: one batch element. Block 128: w_cat column norms.
__global__ __launch_bounds__(NT, 1)
void loss_main(const float* __restrict__ input,
               const float* __restrict__ target,
               const float* __restrict__ normals,
               const float* __restrict__ param_mean,
               const float* __restrict__ param_std,
               const float* __restrict__ u,
               const float* __restrict__ w_shp,
               const float* __restrict__ w_exp,
               const int*   __restrict__ keyindex,
               const int*   __restrict__ ridx_w,
               const int*   __restrict__ ridx_v,
               float* __restrict__ out)
{
    const int tid  = threadIdx.x;
    const int lane = tid & 31;
    const int wid  = tid >> 5;

    // ============ dedicated block: batch-independent w_cat column norms ============
    if (blockIdx.x == BATCH) {
        __shared__ int srow[600];
        __shared__ float cpart[16][50];
        for (int l = tid; l < 600; l += NT) {
            int j = l / 3, c = l - 3 * j;
            int vid = (j < 68) ? keyindex[j] : ridx_w[j - 68];
            srow[l] = 3 * vid + c;
        }
        __syncthreads();
        float a1 = 0.f, a2 = 0.f;
        const int c1 = lane;
        const int c2 = lane + 32;
#pragma unroll 2
        for (int rr = wid; rr < 600; rr += 16) {
            size_t r = (size_t)srow[rr];
            float v1 = w_shp[r * 40 + c1];
            a1 += v1 * v1;
            if (c2 < 50) {
                float v2 = (c2 < 40) ? w_shp[r * 40 + c2] : w_exp[r * 10 + (c2 - 40)];
                a2 += v2 * v2;
            }
        }
        cpart[wid][c1] = a1;
        if (c2 < 50) cpart[wid][c2] = a2;
        __syncthreads();
        if (tid < 50) {
            float s = 0.f;
#pragma unroll
            for (int w = 0; w < 16; w++) s += cpart[w][tid];
            g_wcol[tid] = sqrtf(s);
        }
        __threadfence();
        __syncthreads();
        if (tid == 0) atomicExch(&g_wflag, 1);
        return;
    }

    // ============ per-batch block ============
    const int n = blockIdx.x;

    __shared__ float sp[62], spg[62];
    __shared__ int   sidx[332];        // [0,68) keyindex | [68,200) ridx_w | [200,332) ridx_v
    __shared__ float bv[600], bvg[600];
    __shared__ float tn_w[16][3];
    __shared__ float4 vt4[200], vtg4[200];
    __shared__ float wsum[16];
    __shared__ int   s_last;

    // ---- 0. params + index preload (concurrent, coalesced) ----
    if (tid < 62) {
        float st = param_std[tid], mn = param_mean[tid];
        sp[tid]  = input [n * 62 + tid] * st + mn;
        spg[tid] = target[n * 62 + tid] * st + mn;
    } else if (tid >= 64 && tid < 396) {
        int j = tid - 64;
        sidx[j] = (j < 68) ? keyindex[j] : (j < 200 ? ridx_w[j - 68] : ridx_v[j - 200]);
    } else if (tid >= 400 && tid < 448) {
        int k = tid - 400;
        tn_w[k / 3][k % 3] = 0.f;   // warps not in gather leave zeros
    }
    __syncthreads();

    // ---- 1. gather on warps 0..14 (tids<480); nwl colsums on warp 15; spin on tid 479. ----
    //   items: [0,396) heavy (ridx_v pred+gt) | [396,996) medium (kmix_w pred) | [996,1200) light (key gt)
    float tn0 = 0.f, tn1 = 0.f, tn2 = 0.f;
    float ns0 = 0.f, ns1 = 0.f, ns2 = 0.f;   // warp-15 normals column partials
    if (tid < 480) {
#pragma unroll 1
        for (int l = tid; l < 1200; l += 480) {
            if (l < 396) {
                int row = 204 + l;
                int j = row / 3, c = row - 3 * j;
                size_t r = 3 * (size_t)sidx[j + 132] + c;   // ridx_v[j-68]
                const float4* w4 = (const float4*)(w_shp + r * 40);
                const float2* e2 = (const float2*)(w_exp + r * 10);
                float uu = u[r];
                float sa = uu, sb = 0.f, ga = uu, gb = 0.f;
#pragma unroll
                for (int q = 0; q < 10; q += 2) {
                    float4 v0 = w4[q], v1 = w4[q + 1];
                    sa += v0.x*sp [12+4*q] + v0.y*sp [13+4*q] + v0.z*sp [14+4*q] + v0.w*sp [15+4*q];
                    sb += v1.x*sp [16+4*q] + v1.y*sp [17+4*q] + v1.z*sp [18+4*q] + v1.w*sp [19+4*q];
                    ga += v0.x*spg[12+4*q] + v0.y*spg[13+4*q] + v0.z*spg[14+4*q] + v0.w*spg[15+4*q];
                    gb += v1.x*spg[16+4*q] + v1.y*spg[17+4*q] + v1.z*spg[18+4*q] + v1.w*spg[19+4*q];
                }
#pragma unroll
                for (int q = 0; q < 5; q++) {
                    float2 v = e2[q];
                    sa += v.x*sp [52+2*q] + v.y*sp [53+2*q];
                    ga += v.x*spg[52+2*q] + v.y*spg[53+2*q];
                }
                bv[row] = sa + sb; bvg[row] = ga + gb;
            } else if (l < 996) {
                int m = l - 396;
                int j = m / 3, c = m - 3 * j;
                size_t r = 3 * (size_t)sidx[j] + c;         // kmix_w row
                const float4* w4 = (const float4*)(w_shp + r * 40);
                const float2* e2 = (const float2*)(w_exp + r * 10);
                float sa = u[r], sb = 0.f;
#pragma unroll
                for (int q = 0; q < 10; q += 2) {
                    float4 v0 = w4[q], v1 = w4[q + 1];
                    sa += v0.x*sp[12+4*q] + v0.y*sp[13+4*q] + v0.z*sp[14+4*q] + v0.w*sp[15+4*q];
                    sb += v1.x*sp[16+4*q] + v1.y*sp[17+4*q] + v1.z*sp[18+4*q] + v1.w*sp[19+4*q];
                }
#pragma unroll
                for (int q = 0; q < 5; q++) {
                    float2 v = e2[q];
                    sa += v.x*sp[52+2*q] + v.y*sp[53+2*q];
                }
                float s = sa + sb;
                if (m < 204) bv[m] = s;
                float s2 = s * s;
                if (c == 0) tn0 += s2; else if (c == 1) tn1 += s2; else tn2 += s2;
            } else {
                int m = l - 996;
                int j = m / 3, c = m - 3 * j;
                size_t r = 3 * (size_t)sidx[j] + c;         // keyindex row
                const float4* w4 = (const float4*)(w_shp + r * 40);
                const float2* e2 = (const float2*)(w_exp + r * 10);
                float ga = u[r], gb = 0.f;
#pragma unroll
                for (int q = 0; q < 10; q += 2) {
                    float4 v0 = w4[q], v1 = w4[q + 1];
                    ga += v0.x*spg[12+4*q] + v0.y*spg[13+4*q] + v0.z*spg[14+4*q] + v0.w*spg[15+4*q];
                    gb += v1.x*spg[16+4*q] + v1.y*spg[17+4*q] + v1.z*spg[18+4*q] + v1.w*spg[19+4*q];
                }
#pragma unroll
                for (int q = 0; q < 5; q++) {
                    float2 v = e2[q];
                    ga += v.x*spg[52+2*q] + v.y*spg[53+2*q];
                }
                bvg[m] = ga + gb;
            }
        }
        tn0 = warp_sum(tn0); tn1 = warp_sum(tn1); tn2 = warp_sum(tn2);
        if (lane == 0) { tn_w[wid][0] = tn0; tn_w[wid][1] = tn1; tn_w[wid][2] = tn2; }
        if (tid == 479) {   // overlap the wcol wait with everyone else's gather tail
            while (atomicAdd(&g_wflag, 0) == 0) __nanosleep(64);
        }
    } else {
        // warp 15: normals column sums (coalesced, high MLP), kept in registers.
        const float* nb = normals + (size_t)n * (68 * 68);
#pragma unroll 4
        for (int i = 0; i < 68; i++) {
            const float* rowp = nb + i * 68;
            ns0 += rowp[lane];
            ns1 += rowp[lane + 32];        // cols 32..63
            if (lane < 4) ns2 += rowp[lane + 64];
        }
    }
    __syncthreads();
    __threadfence();  // acquire for g_wcol

    // ---- 2. warp 0: weights + wpdc; tids 256..455: rotate verts ----
    float tot = 0.f;
    if (wid == 0) {
        int p1 = lane, p2 = lane + 32;
        float wj1, wj2 = 0.f;
        {
            float pd = fabsf(sp[p1] - spg[p1]);
            if (p1 < 11) {
                int cc = p1 & 3;
                float sc;
                if (cc < 3) {
                    float t = 0.f;
#pragma unroll
                    for (int w = 0; w < 16; w++) t += tn_w[w][cc];
                    sc = sqrtf(t);
                } else sc = 14.142135623730951f;   // sqrt(200)
                wj1 = pd * sc + 1e-6f;
            } else if (p1 == 11) wj1 = 1e-6f;
            else wj1 = 0.00057339936f * pd * g_wcol[p1 - 12] + 1e-6f;
        }
        if (p2 < 62) {
            float pd = fabsf(sp[p2] - spg[p2]);
            wj2 = 0.00057339936f * pd * g_wcol[p2 - 12] + 1e-6f;
        }
        float m = fmaxf(wj1, wj2);
#pragma unroll
        for (int o = 16; o; o >>= 1) m = fmaxf(m, __shfl_xor_sync(0xffffffffu, m, o));
        float wpdc = 0.f;
        if (p1 != 11) {
            float d = input[n * 62 + p1] - target[n * 62 + p1];
            wpdc += (wj1 / m) * d * d;
        }
        if (p2 < 62) {
            float d = input[n * 62 + p2] - target[n * 62 + p2];
            wpdc += (wj2 / m) * d * d;
        }
        tot += wpdc * (1.f / (128.f * 62.f));
    } else if (tid >= 256 && tid < 456) {
        int t = tid - 256;
        float b0 = bv [3*t], b1 = bv [3*t+1], b2 = bv [3*t+2];
        float c0 = bvg[3*t], c1 = bvg[3*t+1], c2 = bvg[3*t+2];
        float4 o1, o2;
        o1.x = sp [0]*b0 + sp [1]*b1 + sp [2]*b2 + sp [3];
        o1.y = sp [4]*b0 + sp [5]*b1 + sp [6]*b2 + sp [7];
        o1.z = sp [8]*b0 + sp [9]*b1 + sp[10]*b2 + sp[11];
        o1.w = 0.f;
        o2.x = spg[0]*c0 + spg[1]*c1 + spg[2]*c2 + spg[3];
        o2.y = spg[4]*c0 + spg[5]*c1 + spg[6]*c2 + spg[7];
        o2.z = spg[8]*c0 + spg[9]*c1 + spg[10]*c2 + spg[11];
        o2.w = 0.f;
        vt4[t] = o1; vtg4[t] = o2;
    }
    __syncthreads();

    // ---- 3. chamfer: warps 1-7 dir-1 (query (wid-1)*32+lane), warps 8-14 dir-2;
    //         warp 15: nwl from register column sums. ----
    const float k_vdc = 3.f * 0.001f / (128.f * 200.f);
    if (wid >= 1 && wid < 8) {
        int t = (wid - 1) * 32 + lane;
        if (t < 200) {
            float4 X = vtg4[t];
            float ma = 3.4e38f, mb = 3.4e38f, mc = 3.4e38f, md = 3.4e38f;
#pragma unroll 2
            for (int k = 0; k < 200; k += 4) {
                float4 a = vt4[k], b = vt4[k+1], c = vt4[k+2], d = vt4[k+3];
                float a0 = X.x-a.x, a1 = X.y-a.y, a2 = X.z-a.z;
                ma = fminf(ma, a0*a0 + a1*a1 + a2*a2);
                float b0 = X.x-b.x, b1 = X.y-b.y, b2 = X.z-b.z;
                mb = fminf(mb, b0*b0 + b1*b1 + b2*b2);
                float c0 = X.x-c.x, c1 = X.y-c.y, c2 = X.z-c.z;
                mc = fminf(mc, c0*c0 + c1*c1 + c2*c2);
                float d0 = X.x-d.x, d1 = X.y-d.y, d2 = X.z-d.z;
                md = fminf(md, d0*d0 + d1*d1 + d2*d2);
            }
            tot += fminf(fminf(ma, mb), fminf(mc, md)) * k_vdc;
        }
    } else if (wid >= 8 && wid < 15) {
        int t = (wid - 8) * 32 + lane;
        if (t < 200) {
            float4 Y = vt4[t];
            float ma = 3.4e38f, mb = 3.4e38f, mc = 3.4e38f, md = 3.4e38f;
#pragma unroll 2
            for (int k = 0; k < 200; k += 4) {
                float4 a = vtg4[k], b = vtg4[k+1], c = vtg4[k+2], d = vtg4[k+3];
                float a0 = a.x-Y.x, a1 = a.y-Y.y, a2 = a.z-Y.z;
                ma = fminf(ma, a0*a0 + a1*a1 + a2*a2);
                float b0 = b.x-Y.x, b1 = b.y-Y.y, b2 = b.z-Y.z;
                mb = fminf(mb, b0*b0 + b1*b1 + b2*b2);
                float c0 = c.x-Y.x, c1 = c.y-Y.y, c2 = c.z-Y.z;
                mc = fminf(mc, c0*c0 + c1*c1 + c2*c2);
                float d0 = d.x-Y.x, d1 = d.y-Y.y, d2 = d.z-Y.z;
                md = fminf(md, d0*d0 + d1*d1 + d2*d2);
            }
            tot += fminf(fminf(ma, mb), fminf(mc, md)) * k_vdc;
        }
    } else if (wid == 15) {
        const float k_nwl = 3.f * 0.001f / (128.f * 68.f * 3.f);
        {
            int t = lane;
            float d0 = vtg4[t].x - vt4[t].x;
            float d1 = vtg4[t].y - vt4[t].y;
            float d2 = vtg4[t].z - vt4[t].z;
            tot += ns0 * (d0*d0 + d1*d1 + d2*d2) * k_nwl;
        }
        {
            int t = lane + 32;
            float d0 = vtg4[t].x - vt4[t].x;
            float d1 = vtg4[t].y - vt4[t].y;
            float d2 = vtg4[t].z - vt4[t].z;
            tot += ns1 * (d0*d0 + d1*d1 + d2*d2) * k_nwl;
        }
        if (lane < 4) {
            int t = lane + 64;
            float d0 = vtg4[t].x - vt4[t].x;
            float d1 = vtg4[t].y - vt4[t].y;
            float d2 = vtg4[t].z - vt4[t].z;
            tot += ns2 * (d0*d0 + d1*d1 + d2*d2) * k_nwl;
        }
    }

    // ---- 4. block reduce + finalize ----
    tot = warp_sum(tot);
    if (lane == 0) wsum[wid] = tot;
    __syncthreads();
    if (tid == 0) {
        float b = 0.f;
#pragma unroll
        for (int w = 0; w < 16; w++) b += wsum[w];
        g_partials[n] = b;
        __threadfence();
        unsigned int old = atomicAdd(&g_count, 1u);
        s_last = (old == BATCH - 1);
    }
    __syncthreads();
    if (s_last) {
        __threadfence();
        if (wid == 0) {
            float v = g_partials[lane] + g_partials[lane + 32]
                    + g_partials[lane + 64] + g_partials[lane + 96];
#pragma unroll
            for (int o = 16; o; o >>= 1) v += __shfl_down_sync(0xffffffffu, v, o);
            if (lane == 0) { out[0] = v; g_count = 0; g_wflag = 0; }
        }
    }
}

extern "C" void kernel_launch(void* const* d_in, const int* in_sizes, int n_in,
                              void* d_out, int out_size)
{
    (void)in_sizes; (void)n_in; (void)out_size;
    loss_main<<<BATCH + 1, NT>>>(
        (const float*)d_in[0],   // input
        (const float*)d_in[1],   // target
        (const float*)d_in[2],   // normals
        (const float*)d_in[3],   // param_mean
        (const float*)d_in[4],   // param_std
        (const float*)d_in[5],   // u
        (const float*)d_in[6],   // w_shp
        (const float*)d_in[7],   // w_exp
        (const int*)d_in[8],     // keyindex
        (const int*)d_in[9],     // resample_idx_w
        (const int*)d_in[10],    // resample_idx_v
        (float*)d_out);
}